// round 12
// baseline (speedup 1.0000x reference)
#include <cuda_runtime.h>
#include <cuda_bf16.h>
#include <cstdint>

// ---------------------------------------------------------------------------
// OrdinalPeakedCELoss — persistent double-buffered pipeline, v4.
//  R11 post-mortem: 37.4us, issue=77.9% but occ=50.5% — smem (41KB) capped
//  residency at 5 blocks/SM. v4 buys the 6th block:
//   * labels no longer staged in smem: coalesced LDG, prefetched one tile
//     ahead into registers (latency hidden under previous tile's compute)
//   * smem 41KB -> 37KB  => 6 blocks/SM (222KB <= 228KB), grid 888
//   * __launch_bounds__(256,6) caps regs at 42
//  Everything else keeps R11's skeleton: TILE=512, 2 rows/thread, padded
//  guard floats for clamp-free neighbor reads, cp.async.bulk + mbarrier ring,
//  lean arithmetic-mask row math, last-block double-precision reduction.
// ---------------------------------------------------------------------------

#define KCLS 9
#define NTHREADS 256
#define TILE 512
#define ROWS_PT 2
#define NSTAGES 2
#define PAD 4                                    /* guard floats each side  */
#define LOG_FLOATS (TILE * KCLS)                 /* 4608 */
#define LOG_BYTES (LOG_FLOATS * 4)               /* 18432 */
#define NBLK 888                                 /* 148 SMs x 6 blocks */

#define ALPHA_C       0.4f
#define W_FAR_C       7.0f
#define DELTA_FAR_C   0.15f
#define W_TAIL_C      9.0f
#define W_LPEAK_C     12.0f
#define PROB_MARGIN_C 0.35f
#define W_EMD_C       1.2f
#define LOG2E_C       1.4426950408889634f
#define LN2_LN9_C     0.31546487678572877f

#define AWF (ALPHA_C * W_FAR_C)
#define AWT (ALPHA_C * W_TAIL_C)
#define AWL (ALPHA_C * W_LPEAK_C)
#define AWE (ALPHA_C * W_EMD_C)

__device__ float        g_partials[NBLK];
__device__ unsigned int g_count = 0;

__device__ __forceinline__ float f_ex2(float x){ float r; asm("ex2.approx.ftz.f32 %0, %1;" : "=f"(r) : "f"(x)); return r; }
__device__ __forceinline__ float f_lg2(float x){ float r; asm("lg2.approx.ftz.f32 %0, %1;" : "=f"(r) : "f"(x)); return r; }
__device__ __forceinline__ float f_rcp(float x){ float r; asm("rcp.approx.ftz.f32 %0, %1;" : "=f"(r) : "f"(x)); return r; }

__device__ __forceinline__ uint32_t smem_u32(const void* p) {
    uint32_t a;
    asm("{ .reg .u64 t; cvta.to.shared.u64 t, %1; cvt.u32.u64 %0, t; }" : "=r"(a) : "l"(p));
    return a;
}

#define MBAR_INIT(bar, cnt) \
    asm volatile("mbarrier.init.shared.b64 [%0], %1;" :: "r"(bar), "r"(cnt) : "memory")
#define MBAR_EXPECT_TX(bar, bytes) \
    asm volatile("mbarrier.arrive.expect_tx.shared.b64 _, [%0], %1;" :: "r"(bar), "r"(bytes) : "memory")
#define MBAR_WAIT(bar, ph) do {                                                   \
    asm volatile("{\n\t.reg .pred P;\n"                                           \
        "W_%=:\n\t"                                                               \
        "mbarrier.try_wait.parity.acquire.cta.shared::cta.b64 P, [%0], %1, 0x989680;\n\t" \
        "@P bra D_%=;\n\t"                                                        \
        "bra W_%=;\n"                                                             \
        "D_%=:\n\t}"                                                              \
        :: "r"(bar), "r"(ph) : "memory");                                         \
} while (0)
#define BULK_CP(dst, src, bytes, bar) \
    asm volatile("cp.async.bulk.shared::cta.global.mbarrier::complete_tx::bytes [%0], [%1], %2, [%3];" \
        :: "r"(dst), "l"(src), "r"(bytes), "r"(bar) : "memory")

__device__ __forceinline__ float cw_of(int k) {
    const float cw[KCLS] = {
        3.0f/95.0f, 7.0f/95.0f, 10.0f/95.0f, 10.0f/95.0f, 10.0f/95.0f,
        10.0f/95.0f, 10.0f/95.0f, 10.0f/95.0f, 25.0f/95.0f };
    return cw[k];
}

// Hot path: lrow must be readable at [-1] and [9] (padded tile guarantees it;
// out-of-row values are finite and masked to zero).
__device__ __forceinline__ float row_loss(const float* __restrict__ lrow, int y,
                                          const float* __restrict__ s_ccw) {
    const float fy  = (float)y;
    const float fy1 = fy + 1.0f;

    float E = 0.0f, Q = 0.0f, A = 0.0f, tail = 0.0f, ef = 0.0f;

#pragma unroll
    for (int k = 0; k < KCLS; ++k) {
        float e = f_ex2(lrow[k] * LOG2E_C);            // exp(l_k)
        E += e;                                         // prefix; E_8 == S
        float u = cw_of(k) * E;                         // FMUL imm
        Q = fmaf(u, E, Q);                              // sum cw_k E_k^2
        float le = __saturatef(fy1 - (float)k);         // 1 iff k<=y
        A = fmaf(le, u, A);
        float s = fabsf((float)k - fy) - 1.0f;          // |d|-1
        float c = fmaxf(s, 0.0f);
        float h = e * c;
        ef = fmaxf(ef, fminf(h, e));                    // e*min(c,1)
        tail = fmaf(h, c * c, tail);                    // e*(|d|-1)^3
    }

    float invS = f_rcp(E);
    float ty = lrow[y] * LOG2E_C;
    float ey = f_ex2(ty);
    float el = f_ex2(lrow[y - 1] * LOG2E_C) * __saturatef(fy);         // 0 at y=0
    float er = f_ex2(lrow[y + 1] * LOG2E_C) * __saturatef(8.0f - fy);  // 0 at y=8
    float en = fmaxf(el, er);

    float farm  = fmaxf(fmaf(ef - ey, invS, DELTA_FAR_C),   0.0f);
    float lpeak = fmaxf(fmaf(en - ey, invS, PROB_MARGIN_C), 0.0f);
    float emd   = fmaf(Q, invS * invS, fmaf(-2.0f * A, invS, s_ccw[y]));

    float r = (f_lg2(E) - ty) * LN2_LN9_C;              // nll / ln 9
    r = fmaf(AWF, farm, r);
    r = fmaf(AWT, tail * invS, r);
    r = fmaf(AWL, lpeak, r);
    r = fmaf(AWE, emd, r);
    return r;
}

// Residue path (rare): clamped indices, direct global reads.
__device__ __noinline__ float row_loss_global(const float* __restrict__ g, int y,
                                              const float* __restrict__ s_ccw) {
    const float fy = (float)y;
    float E = 0.0f, Q = 0.0f, A = 0.0f, tail = 0.0f, ef = 0.0f;
    float lv[KCLS];
#pragma unroll
    for (int k = 0; k < KCLS; ++k) lv[k] = __ldg(&g[k]);
#pragma unroll
    for (int k = 0; k < KCLS; ++k) {
        float e = f_ex2(lv[k] * LOG2E_C);
        E += e;
        float u = cw_of(k) * E;
        Q = fmaf(u, E, Q);
        float le = __saturatef(fy + 1.0f - (float)k);
        A = fmaf(le, u, A);
        float s = fabsf((float)k - fy) - 1.0f;
        float c = fmaxf(s, 0.0f);
        float h = e * c;
        ef = fmaxf(ef, fminf(h, e));
        tail = fmaf(h, c * c, tail);
    }
    float invS = f_rcp(E);
    int yl = (y > 0) ? y - 1 : 0;
    int yr = (y < KCLS - 1) ? y + 1 : KCLS - 1;
    float ty = lv[y] * LOG2E_C;
    float ey = f_ex2(ty);
    float el = f_ex2(lv[yl] * LOG2E_C) * __saturatef(fy);
    float er = f_ex2(lv[yr] * LOG2E_C) * __saturatef(8.0f - fy);
    float en = fmaxf(el, er);
    float farm  = fmaxf(fmaf(ef - ey, invS, DELTA_FAR_C),   0.0f);
    float lpeak = fmaxf(fmaf(en - ey, invS, PROB_MARGIN_C), 0.0f);
    float emd   = fmaf(Q, invS * invS, fmaf(-2.0f * A, invS, s_ccw[y]));
    float r = (f_lg2(E) - ty) * LN2_LN9_C;
    r = fmaf(AWF, farm, r);
    r = fmaf(AWT, tail * invS, r);
    r = fmaf(AWL, lpeak, r);
    r = fmaf(AWE, emd, r);
    return r;
}

__global__ __launch_bounds__(NTHREADS, 6)
void opcel_pipe(const float* __restrict__ logits,
                const int*   __restrict__ y,
                float*       __restrict__ out,
                int B, int nblocks) {
    /* +2*PAD guard floats per stage; bulk copy lands at +PAD (16B aligned) */
    __shared__ __align__(16) float s_log[NSTAGES][LOG_FLOATS + 2 * PAD];
    __shared__ __align__(8)  unsigned long long s_bar[NSTAGES];
    __shared__ float s_ccw[KCLS];
    __shared__ float s_red[NTHREADS / 32];
    __shared__ int   s_last;

    const int tid = threadIdx.x;
    const int bid = blockIdx.x;

    if (tid < KCLS) {
        const float ccw[KCLS] = {
            3.0f/95.0f, 10.0f/95.0f, 20.0f/95.0f, 30.0f/95.0f, 40.0f/95.0f,
            50.0f/95.0f, 60.0f/95.0f, 70.0f/95.0f, 1.0f };
        s_ccw[tid] = ccw[tid];
    }
    // Zero the guard pads once (never touched by bulk copies afterwards).
    if (tid < PAD) {
#pragma unroll
        for (int s = 0; s < NSTAGES; ++s) {
            s_log[s][tid] = 0.0f;
            s_log[s][PAD + LOG_FLOATS + tid] = 0.0f;
        }
    }

    const uint32_t bar0 = smem_u32(&s_bar[0]);
    const uint32_t bar1 = smem_u32(&s_bar[1]);
    const uint32_t d_log0 = smem_u32(&s_log[0][PAD]);
    const uint32_t d_log1 = smem_u32(&s_log[1][PAD]);

    if (tid == 0) { MBAR_INIT(bar0, 1); MBAR_INIT(bar1, 1); }
    __syncthreads();

    const int ntiles = B / TILE;
    int my_n = 0;
    for (long long t = bid; t < ntiles; t += nblocks) ++my_n;

    // Prologue: kick tile 0's bulk copy; prefetch tile 0's labels to regs.
    int yc0 = 0, yc1 = 0;
    if (my_n > 0) {
        long long t0 = bid;
        if (tid == 0) {
            MBAR_EXPECT_TX(bar0, LOG_BYTES);
            BULK_CP(d_log0, (const void*)(logits + t0 * (TILE * KCLS)), LOG_BYTES, bar0);
        }
        const int* yp = y + t0 * TILE;
        yc0 = __ldg(&yp[tid]);
        yc1 = __ldg(&yp[tid + NTHREADS]);
    }

    float acc = 0.0f;
    int ph0 = 0, ph1 = 0;

    for (int j = 0; j < my_n; ++j) {
        const int s = j & 1;
        int yn0 = 0, yn1 = 0;
        if ((j + 1) < my_n) {
            long long tn = (long long)bid + (long long)(j + 1) * nblocks;
            if (tid == 0) {
                if (s == 0) {
                    MBAR_EXPECT_TX(bar1, LOG_BYTES);
                    BULK_CP(d_log1, (const void*)(logits + tn * (TILE * KCLS)), LOG_BYTES, bar1);
                } else {
                    MBAR_EXPECT_TX(bar0, LOG_BYTES);
                    BULK_CP(d_log0, (const void*)(logits + tn * (TILE * KCLS)), LOG_BYTES, bar0);
                }
            }
            // Prefetch next tile's labels now; consumed only next iteration,
            // so the LDG latency hides under this tile's compute.
            const int* yp = y + tn * TILE;
            yn0 = __ldg(&yp[tid]);
            yn1 = __ldg(&yp[tid + NTHREADS]);
        }

        if (s == 0) { MBAR_WAIT(bar0, ph0); ph0 ^= 1; }
        else        { MBAR_WAIT(bar1, ph1); ph1 ^= 1; }

        const float* lg = &s_log[s][PAD];
        acc += row_loss(lg + tid * KCLS, yc0, s_ccw);
        acc += row_loss(lg + (tid + NTHREADS) * KCLS, yc1, s_ccw);
        __syncthreads();                        /* all lanes done reading stage s */

        yc0 = yn0; yc1 = yn1;
    }

    // Residue rows (B % TILE) -> block 0, direct global reads.
    if (bid == 0) {
        for (int r = ntiles * TILE + tid; r < B; r += NTHREADS)
            acc += row_loss_global(logits + (long long)r * KCLS, __ldg(&y[r]), s_ccw);
    }

    // Block reduction
#pragma unroll
    for (int off = 16; off > 0; off >>= 1)
        acc += __shfl_down_sync(0xFFFFFFFFu, acc, off);
    int lane = tid & 31, wid = tid >> 5;
    if (lane == 0) s_red[wid] = acc;
    __syncthreads();
    if (tid == 0) {
        float v = 0.0f;
#pragma unroll
        for (int w = 0; w < NTHREADS / 32; ++w) v += s_red[w];
        g_partials[bid] = v;
        __threadfence();
        unsigned int t = atomicAdd(&g_count, 1u);
        s_last = (t == (unsigned int)(nblocks - 1));
    }
    __syncthreads();

    // Last block: deterministic final reduction in double
    if (s_last) {
        double d = 0.0;
        for (int i = tid; i < nblocks; i += NTHREADS)
            d += (double)g_partials[i];
#pragma unroll
        for (int off = 16; off > 0; off >>= 1)
            d += __shfl_down_sync(0xFFFFFFFFu, d, off);

        __shared__ double s_d[NTHREADS / 32];
        if (lane == 0) s_d[wid] = d;
        __syncthreads();
        if (tid == 0) {
            double tot = 0.0;
#pragma unroll
            for (int w = 0; w < NTHREADS / 32; ++w) tot += s_d[w];
            out[0] = (float)(tot / (double)B);
            g_count = 0;   /* self-reset for graph replay */
        }
    }
}

extern "C" void kernel_launch(void* const* d_in, const int* in_sizes, int n_in,
                              void* d_out, int out_size) {
    const float* logits = (const float*)d_in[0];
    const int*   y      = (const int*)d_in[1];
    float* out = (float*)d_out;
    int B = in_sizes[1];

    int ntiles = B / TILE;
    int nblocks = NBLK;
    if (nblocks > ntiles && ntiles > 0) nblocks = ntiles;
    if (nblocks < 1) nblocks = 1;

    opcel_pipe<<<nblocks, NTHREADS>>>(logits, y, out, B, nblocks);
}

// round 13
// speedup vs baseline: 1.0156x; 1.0156x over previous
#include <cuda_runtime.h>
#include <cuda_bf16.h>
#include <cstdint>

// ---------------------------------------------------------------------------
// OrdinalPeakedCELoss — warp-autonomous double-buffered pipeline (v5).
//  R12 post-mortem: block-wide sync + shared mbarrier couple all 8 warps to
//  the slowest; extra occupancy couldn't fill the bubbles (issue fell 78->70).
//  v5 removes the coupling:
//   * per-warp tile slices (64 rows), per-warp mbarriers, per-warp bulk
//     copies -> NO __syncthreads in the main loop; warps fully self-paced
//   * tail & far-mask from an 81-float scalar-LDS LUT (conflict-free banks):
//     per-class block 16 -> 13 instructions;  farmask == min(tw,1) exactly
//   * R11 proven shell: 740 blocks, TILE=512, ~41KB smem, 5 blocks/SM,
//     padded guards for clamp-free neighbor reads, last-block double sum.
// ---------------------------------------------------------------------------

#define KCLS 9
#define NTHREADS 256
#define NWARPS (NTHREADS / 32)
#define TILE 512
#define SLICE_ROWS 64                            /* rows per warp slice   */
#define SLICE_F (SLICE_ROWS * KCLS)              /* 576 floats = 2304 B   */
#define SLICE_BYTES (SLICE_F * 4)
#define YSLICE_BYTES (SLICE_ROWS * 4)            /* 256 B                 */
#define TX_BYTES (SLICE_BYTES + YSLICE_BYTES)    /* 2560                  */
#define NSTAGES 2
#define PAD 4
#define NBLK 740

#define ALPHA_C       0.4f
#define W_FAR_C       7.0f
#define DELTA_FAR_C   0.15f
#define W_TAIL_C      9.0f
#define W_LPEAK_C     12.0f
#define PROB_MARGIN_C 0.35f
#define W_EMD_C       1.2f
#define LOG2E_C       1.4426950408889634f
#define LN2_LN9_C     0.31546487678572877f

#define AWF (ALPHA_C * W_FAR_C)
#define AWT (ALPHA_C * W_TAIL_C)
#define AWL (ALPHA_C * W_LPEAK_C)
#define AWE (ALPHA_C * W_EMD_C)

__device__ float        g_partials[NBLK];
__device__ unsigned int g_count = 0;

__device__ __forceinline__ float f_ex2(float x){ float r; asm("ex2.approx.ftz.f32 %0, %1;" : "=f"(r) : "f"(x)); return r; }
__device__ __forceinline__ float f_lg2(float x){ float r; asm("lg2.approx.ftz.f32 %0, %1;" : "=f"(r) : "f"(x)); return r; }
__device__ __forceinline__ float f_rcp(float x){ float r; asm("rcp.approx.ftz.f32 %0, %1;" : "=f"(r) : "f"(x)); return r; }

__device__ __forceinline__ uint32_t smem_u32(const void* p) {
    uint32_t a;
    asm("{ .reg .u64 t; cvta.to.shared.u64 t, %1; cvt.u32.u64 %0, t; }" : "=r"(a) : "l"(p));
    return a;
}

#define MBAR_INIT(bar, cnt) \
    asm volatile("mbarrier.init.shared.b64 [%0], %1;" :: "r"(bar), "r"(cnt) : "memory")
#define MBAR_EXPECT_TX(bar, bytes) \
    asm volatile("mbarrier.arrive.expect_tx.shared.b64 _, [%0], %1;" :: "r"(bar), "r"(bytes) : "memory")
#define MBAR_WAIT(bar, ph) do {                                                   \
    asm volatile("{\n\t.reg .pred P;\n"                                           \
        "W_%=:\n\t"                                                               \
        "mbarrier.try_wait.parity.acquire.cta.shared::cta.b64 P, [%0], %1, 0x989680;\n\t" \
        "@P bra D_%=;\n\t"                                                        \
        "bra W_%=;\n"                                                             \
        "D_%=:\n\t}"                                                              \
        :: "r"(bar), "r"(ph) : "memory");                                         \
} while (0)
#define BULK_CP(dst, src, bytes, bar) \
    asm volatile("cp.async.bulk.shared::cta.global.mbarrier::complete_tx::bytes [%0], [%1], %2, [%3];" \
        :: "r"(dst), "l"(src), "r"(bytes), "r"(bar) : "memory")

__device__ __forceinline__ float cw_of(int k) {
    const float cw[KCLS] = {
        3.0f/95.0f, 7.0f/95.0f, 10.0f/95.0f, 10.0f/95.0f, 10.0f/95.0f,
        10.0f/95.0f, 10.0f/95.0f, 10.0f/95.0f, 25.0f/95.0f };
    return cw[k];
}

// Hot path.  lrow readable at [-1] and [9]; tw = s_tw + y*9.
__device__ __forceinline__ float row_loss(const float* __restrict__ lrow, int y,
                                          const float* __restrict__ tw,
                                          const float* __restrict__ s_ccw) {
    const float fy  = (float)y;
    const float fy1 = fy + 1.0f;

    float E = 0.0f, Q = 0.0f, A = 0.0f, tail = 0.0f, ef = 0.0f;

#pragma unroll
    for (int k = 0; k < KCLS; ++k) {
        float e = f_ex2(lrow[k] * LOG2E_C);            // exp(l_k)
        E += e;                                         // prefix; E_8 == S
        float u = cw_of(k) * E;                         // FMUL imm
        Q = fmaf(u, E, Q);                              // sum cw_k E_k^2
        float le = __saturatef(fy1 - (float)k);         // 1 iff k<=y
        A = fmaf(le, u, A);
        float w = tw[k];                                // (|d|-1)^3 or 0 (LDS)
        float h = e * w;
        tail += h;                                      // e*(|d|-1)^3
        ef = fmaxf(ef, fminf(h, e));                    // e * min(w,1): far max
    }

    float invS = f_rcp(E);
    float ty = lrow[y] * LOG2E_C;
    float ey = f_ex2(ty);
    float el = f_ex2(lrow[y - 1] * LOG2E_C) * __saturatef(fy);         // 0 at y=0
    float er = f_ex2(lrow[y + 1] * LOG2E_C) * __saturatef(8.0f - fy);  // 0 at y=8
    float en = fmaxf(el, er);

    float farm  = fmaxf(fmaf(ef - ey, invS, DELTA_FAR_C),   0.0f);
    float lpeak = fmaxf(fmaf(en - ey, invS, PROB_MARGIN_C), 0.0f);
    float emd   = fmaf(Q, invS * invS, fmaf(-2.0f * A, invS, s_ccw[y]));

    float r = (f_lg2(E) - ty) * LN2_LN9_C;              // nll / ln 9
    r = fmaf(AWF, farm, r);
    r = fmaf(AWT, tail * invS, r);
    r = fmaf(AWL, lpeak, r);
    r = fmaf(AWE, emd, r);
    return r;
}

// Residue path (rare): clamped indices, direct global reads.
__device__ __noinline__ float row_loss_global(const float* __restrict__ g, int y,
                                              const float* __restrict__ s_ccw) {
    const float fy = (float)y;
    float E = 0.0f, Q = 0.0f, A = 0.0f, tail = 0.0f, ef = 0.0f;
    float lv[KCLS];
#pragma unroll
    for (int k = 0; k < KCLS; ++k) lv[k] = __ldg(&g[k]);
#pragma unroll
    for (int k = 0; k < KCLS; ++k) {
        float e = f_ex2(lv[k] * LOG2E_C);
        E += e;
        float u = cw_of(k) * E;
        Q = fmaf(u, E, Q);
        float le = __saturatef(fy + 1.0f - (float)k);
        A = fmaf(le, u, A);
        float s = fabsf((float)k - fy) - 1.0f;
        float c = fmaxf(s, 0.0f);
        float h = e * c;
        ef = fmaxf(ef, fminf(h, e));
        tail = fmaf(h, c * c, tail);
    }
    float invS = f_rcp(E);
    int yl = (y > 0) ? y - 1 : 0;
    int yr = (y < KCLS - 1) ? y + 1 : KCLS - 1;
    float ty = lv[y] * LOG2E_C;
    float ey = f_ex2(ty);
    float el = f_ex2(lv[yl] * LOG2E_C) * __saturatef(fy);
    float er = f_ex2(lv[yr] * LOG2E_C) * __saturatef(8.0f - fy);
    float en = fmaxf(el, er);
    float farm  = fmaxf(fmaf(ef - ey, invS, DELTA_FAR_C),   0.0f);
    float lpeak = fmaxf(fmaf(en - ey, invS, PROB_MARGIN_C), 0.0f);
    float emd   = fmaf(Q, invS * invS, fmaf(-2.0f * A, invS, s_ccw[y]));
    float r = (f_lg2(E) - ty) * LN2_LN9_C;
    r = fmaf(AWF, farm, r);
    r = fmaf(AWT, tail * invS, r);
    r = fmaf(AWL, lpeak, r);
    r = fmaf(AWE, emd, r);
    return r;
}

__global__ __launch_bounds__(NTHREADS, 5)
void opcel_pipe(const float* __restrict__ logits,
                const int*   __restrict__ y,
                float*       __restrict__ out,
                int B, int nblocks) {
    // One contiguous logit buffer: [PAD | stage0: 8 slices | stage1: 8 slices | PAD]
    __shared__ __align__(16) float s_logbuf[2 * PAD + NSTAGES * NWARPS * SLICE_F];
    __shared__ __align__(16) int   s_y[NSTAGES][NWARPS][SLICE_ROWS];
    __shared__ __align__(8)  unsigned long long s_bar[NSTAGES][NWARPS];
    __shared__ float s_tw[KCLS * KCLS];          /* tail LUT [y*9+k] */
    __shared__ float s_ccw[KCLS];
    __shared__ float s_red[NWARPS];
    __shared__ int   s_last;

    const int tid  = threadIdx.x;
    const int bid  = blockIdx.x;
    const int wid  = tid >> 5;
    const int lane = tid & 31;

    if (tid < KCLS) {
        const float ccw[KCLS] = {
            3.0f/95.0f, 10.0f/95.0f, 20.0f/95.0f, 30.0f/95.0f, 40.0f/95.0f,
            50.0f/95.0f, 60.0f/95.0f, 70.0f/95.0f, 1.0f };
        s_ccw[tid] = ccw[tid];
    }
    if (tid < KCLS * KCLS) {
        int yv = tid / KCLS, k = tid - yv * KCLS;
        int d = k - yv; int ad = (d < 0) ? -d : d;
        float w = 0.0f;
        if (ad > 1) { float q = (float)(ad - 1); w = q * q * q; }
        s_tw[tid] = w;
    }
    if (tid < PAD) {
        s_logbuf[tid] = 0.0f;
        s_logbuf[PAD + NSTAGES * NWARPS * SLICE_F + tid] = 0.0f;
    }
    if (tid < NSTAGES * NWARPS) {
        MBAR_INIT(smem_u32(&s_bar[tid / NWARPS][tid % NWARPS]), 1);
    }
    __syncthreads();

    // Per-warp slice bases
    const uint32_t barw[2] = { smem_u32(&s_bar[0][wid]), smem_u32(&s_bar[1][wid]) };
    float* slice[2] = {
        &s_logbuf[PAD + (0 * NWARPS + wid) * SLICE_F],
        &s_logbuf[PAD + (1 * NWARPS + wid) * SLICE_F] };
    const uint32_t d_log[2] = { smem_u32(slice[0]), smem_u32(slice[1]) };
    const uint32_t d_y[2]   = { smem_u32(&s_y[0][wid][0]), smem_u32(&s_y[1][wid][0]) };

    const int ntiles = B / TILE;
    int my_n = 0;
    for (long long t = bid; t < ntiles; t += nblocks) ++my_n;

    // Prologue: warp's slice of tile 0.
    if (my_n > 0 && lane == 0) {
        long long t0 = bid;
        const float* src_l = logits + t0 * (TILE * KCLS) + wid * SLICE_F;
        const int*   src_y = y + t0 * TILE + wid * SLICE_ROWS;
        MBAR_EXPECT_TX(barw[0], TX_BYTES);
        BULK_CP(d_log[0], (const void*)src_l, SLICE_BYTES, barw[0]);
        BULK_CP(d_y[0],   (const void*)src_y, YSLICE_BYTES, barw[0]);
    }

    float acc = 0.0f;
    int ph0 = 0, ph1 = 0;

    for (int j = 0; j < my_n; ++j) {
        const int s = j & 1;
        // Issue next slice copy into the other stage (this warp consumed it
        // in iteration j-1; warp-synchronous => no barrier needed).
        if (lane == 0 && (j + 1) < my_n) {
            long long tn = (long long)bid + (long long)(j + 1) * nblocks;
            const int ns = s ^ 1;
            const float* src_l = logits + tn * (TILE * KCLS) + wid * SLICE_F;
            const int*   src_y = y + tn * TILE + wid * SLICE_ROWS;
            MBAR_EXPECT_TX(barw[ns], TX_BYTES);
            BULK_CP(d_log[ns], (const void*)src_l, SLICE_BYTES, barw[ns]);
            BULK_CP(d_y[ns],   (const void*)src_y, YSLICE_BYTES, barw[ns]);
        }

        if (s == 0) { MBAR_WAIT(barw[0], ph0); ph0 ^= 1; }
        else        { MBAR_WAIT(barw[1], ph1); ph1 ^= 1; }

        const float* lg = slice[s];
        const int*   yt = s_y[s][wid];
        {
            int r0 = lane, r1 = lane + 32;       /* stride-9-word rows: conflict-free */
            int y0 = yt[r0], y1 = yt[r1];
            acc += row_loss(lg + r0 * KCLS, y0, s_tw + y0 * KCLS, s_ccw);
            acc += row_loss(lg + r1 * KCLS, y1, s_tw + y1 * KCLS, s_ccw);
        }
        /* no __syncthreads: warp is sole reader/writer of its slices */
    }

    // Residue rows (B % TILE) -> block 0, direct global reads.
    if (bid == 0) {
        for (int r = ntiles * TILE + tid; r < B; r += NTHREADS)
            acc += row_loss_global(logits + (long long)r * KCLS, __ldg(&y[r]), s_ccw);
    }

    // Block reduction
#pragma unroll
    for (int off = 16; off > 0; off >>= 1)
        acc += __shfl_down_sync(0xFFFFFFFFu, acc, off);
    if (lane == 0) s_red[wid] = acc;
    __syncthreads();
    if (tid == 0) {
        float v = 0.0f;
#pragma unroll
        for (int w = 0; w < NWARPS; ++w) v += s_red[w];
        g_partials[bid] = v;
        __threadfence();
        unsigned int t = atomicAdd(&g_count, 1u);
        s_last = (t == (unsigned int)(nblocks - 1));
    }
    __syncthreads();

    // Last block: deterministic final reduction in double
    if (s_last) {
        double d = 0.0;
        for (int i = tid; i < nblocks; i += NTHREADS)
            d += (double)g_partials[i];
#pragma unroll
        for (int off = 16; off > 0; off >>= 1)
            d += __shfl_down_sync(0xFFFFFFFFu, d, off);

        __shared__ double s_d[NWARPS];
        if (lane == 0) s_d[wid] = d;
        __syncthreads();
        if (tid == 0) {
            double tot = 0.0;
#pragma unroll
            for (int w = 0; w < NWARPS; ++w) tot += s_d[w];
            out[0] = (float)(tot / (double)B);
            g_count = 0;   /* self-reset for graph replay */
        }
    }
}

extern "C" void kernel_launch(void* const* d_in, const int* in_sizes, int n_in,
                              void* d_out, int out_size) {
    const float* logits = (const float*)d_in[0];
    const int*   y      = (const int*)d_in[1];
    float* out = (float*)d_out;
    int B = in_sizes[1];

    int ntiles = B / TILE;
    int nblocks = NBLK;
    if (nblocks > ntiles && ntiles > 0) nblocks = ntiles;
    if (nblocks < 1) nblocks = 1;

    opcel_pipe<<<nblocks, NTHREADS>>>(logits, y, out, B, nblocks);
}